// round 13
// baseline (speedup 1.0000x reference)
#include <cuda_runtime.h>
#include <cuda_bf16.h>
#include <math.h>
#include <stdint.h>

#define NB 16
#define ND 256
#define NL 256
#define NT 1000
#define NCH 8
#define NDW 4
#define NDC 2

// ---------------- scratch (device globals; no allocations allowed) ----------
__device__ __align__(16) float g_sd[NB * NL];
__device__ __align__(16) float g_sk[NB * NL];
__device__ int g_flen[NB];
__device__ __align__(16) float g_weff[ND * 48];       // [d][br*8+ch][k]
__device__ __align__(16) float g_cwpb[48];            // [br][ch][k]
__device__ __align__(16) float g_hpart[32 * NB * NL * 16]; // [chunk][(b*L+l)*16+idx]
__device__ __align__(16) float g_bzw[NB * NL * 4];    // t-invariant w-logit base
__device__ __align__(16) float g_bzc[NB * NL * 2];    // t-invariant c base
__device__ __align__(16) float g_pad[NB * NL];        // 1.0 if phone_pad
// M panel, bf16x2-packed over K-pairs; K order is q-major: k = q*256 + l
// g_Mp[b][kk][o] packs rows k=2kk (lo) and k=2kk+1 (hi)
__device__ __align__(16) uint32_t g_Mp[(size_t)NB * 512 * 256];

__device__ __forceinline__ float swishf(float z) {
    return z / (1.0f + expf(-z));
}
__device__ __forceinline__ float tanh_approx(float x) {
    float y; asm("tanh.approx.f32 %0, %1;" : "=f"(y) : "f"(x)); return y;
}
__device__ __forceinline__ float swish_t(float z) {
    return z * (0.5f + 0.5f * tanh_approx(0.5f * z));
}
__device__ __forceinline__ float to_tf32(float x) {
    uint32_t u;
    asm("cvt.rna.tf32.f32 %0, %1;" : "=r"(u) : "f"(x));
    return __uint_as_float(u);
}
__device__ __forceinline__ uint32_t pack_bf16(float lo, float hi) {
    uint32_t u;
    asm("cvt.rn.bf16x2.f32 %0, %1, %2;" : "=r"(u) : "f"(hi), "f"(lo));
    return u;
}
__device__ __forceinline__ void mma_tf32(float c[4], uint32_t a0, uint32_t a1,
                                         uint32_t a2, uint32_t a3,
                                         uint32_t b0, uint32_t b1) {
    asm volatile(
        "mma.sync.aligned.m16n8k8.row.col.f32.tf32.tf32.f32 "
        "{%0,%1,%2,%3}, {%4,%5,%6,%7}, {%8,%9}, {%0,%1,%2,%3};\n"
        : "+f"(c[0]), "+f"(c[1]), "+f"(c[2]), "+f"(c[3])
        : "r"(a0), "r"(a1), "r"(a2), "r"(a3), "r"(b0), "r"(b1));
}
__device__ __forceinline__ void mma_bf16(float c[4], uint32_t a0, uint32_t a1,
                                         uint32_t a2, uint32_t a3,
                                         uint32_t b0, uint32_t b1) {
    asm volatile(
        "mma.sync.aligned.m16n8k16.row.col.f32.bf16.bf16.f32 "
        "{%0,%1,%2,%3}, {%4,%5,%6,%7}, {%8,%9}, {%0,%1,%2,%3};\n"
        : "+f"(c[0]), "+f"(c[1]), "+f"(c[2]), "+f"(c[3])
        : "r"(a0), "r"(a1), "r"(a2), "r"(a3), "r"(b0), "r"(b1));
}

// ---------------- K1: cumsum scan, frame_len ------------------------------
__global__ void k_scan(const float* __restrict__ dur) {
    int b = blockIdx.x, l = threadIdx.x;
    __shared__ float s[NL];
    float x = dur[b * NL + l];
    s[l] = x;
    __syncthreads();
#pragma unroll
    for (int off = 1; off < NL; off <<= 1) {
        float v = (l >= off) ? s[l - off] : 0.0f;
        __syncthreads();
        s[l] += v;
        __syncthreads();
    }
    float sd = s[l];
    g_sd[b * NL + l] = sd;
    g_sk[b * NL + l] = sd - x;
    if (l == 0) {
        float tot = s[NL - 1];
        int fl = (int)rintf(tot);
        if (fl < 0) fl = 0;
        if (fl > NT) fl = NT;
        g_flen[b] = fl;
    }
}

// ---------------- K2: fold projection into conv weights -------------------
__global__ void k_weff(const float* __restrict__ pwW, const float* __restrict__ cwW,
                       const float* __restrict__ pcW, const float* __restrict__ ccW) {
    int k = blockIdx.x, ch = blockIdx.y, br = blockIdx.z, d = threadIdx.x;
    const float* cw = br ? ccW : cwW;
    const float* pw = br ? pcW : pwW;
    float acc = 0.0f;
#pragma unroll 4
    for (int o = 0; o < ND; o++)
        acc += cw[(ch * ND + o) * 3 + k] * pw[o * ND + d];
    g_weff[d * 48 + (br * 8 + ch) * 3 + k] = acc;
}

__global__ void k_cwpb(const float* __restrict__ cwW, const float* __restrict__ pwb,
                       const float* __restrict__ ccW, const float* __restrict__ pcb) {
    int i = threadIdx.x;
    if (i >= 48) return;
    int br = i / 24, rem = i % 24, ch = rem / 3, k = rem % 3;
    const float* cw = br ? ccW : cwW;
    const float* pb = br ? pcb : pwb;
    float a = 0.0f;
    for (int o = 0; o < ND; o++) a += cw[(ch * ND + o) * 3 + k] * pb[o];
    g_cwpb[i] = a;
}

// ---------------- K3a: partial conv over 8-d chunks -----------------------
__global__ void k_conv_part(const float* __restrict__ ph) {
    int b = blockIdx.x, c = blockIdx.y, l = threadIdx.x;
    __shared__ __align__(16) float sWe[8 * 48];
    for (int i = l; i < 8 * 48; i += NL) sWe[i] = g_weff[c * 8 * 48 + i];
    __syncthreads();

    const float* phb = ph + (size_t)b * ND * NL + (size_t)(c * 8) * NL;
    float acc[16];
#pragma unroll
    for (int i = 0; i < 16; i++) acc[i] = 0.0f;

#pragma unroll
    for (int dd = 0; dd < 8; dd++) {
        float vm = (l > 0) ? phb[dd * NL + l - 1] : 0.0f;
        float v0 = phb[dd * NL + l];
        float vp = (l < NL - 1) ? phb[dd * NL + l + 1] : 0.0f;
        float v[3] = {vm, v0, vp};
        const float* wd = sWe + dd * 48;
#pragma unroll
        for (int lin = 0; lin < 48; lin += 4) {
            float4 w = *(const float4*)(wd + lin);
            acc[(lin + 0) / 3] += w.x * v[(lin + 0) % 3];
            acc[(lin + 1) / 3] += w.y * v[(lin + 1) % 3];
            acc[(lin + 2) / 3] += w.z * v[(lin + 2) % 3];
            acc[(lin + 3) / 3] += w.w * v[(lin + 3) % 3];
        }
    }
    float* outp = g_hpart + ((size_t)(c * NB + b) * NL + l) * 16;
#pragma unroll
    for (int i = 0; i < 16; i += 4)
        *(float4*)(outp + i) = make_float4(acc[i], acc[i + 1], acc[i + 2], acc[i + 3]);
}

// ---- K3b: reduce partials + bias + swish, fold h into t-invariant bases --
__global__ void k_conv_fin(const float* __restrict__ dur,
                           const float* __restrict__ cwb, const float* __restrict__ ccb,
                           const float* __restrict__ mwW, const float* __restrict__ mwb,
                           const float* __restrict__ mcW, const float* __restrict__ mcb) {
    int b = blockIdx.x, l = threadIdx.x;
    __shared__ float smw[40], smwb[4], smc[20], smcb[2];
    if (l < 40) smw[l] = mwW[l];
    if (l < 4) smwb[l] = mwb[l];
    if (l >= 64 && l < 84) smc[l - 64] = mcW[l - 64];
    if (l >= 96 && l < 98) smcb[l - 96] = mcb[l - 96];

    float acc[16];
#pragma unroll
    for (int i = 0; i < 16; i++) acc[i] = 0.0f;
#pragma unroll
    for (int c = 0; c < 32; c++) {
        const float* p = g_hpart + ((size_t)(c * NB + b) * NL + l) * 16;
#pragma unroll
        for (int i = 0; i < 16; i += 4) {
            float4 v = *(const float4*)(p + i);
            acc[i] += v.x; acc[i + 1] += v.y; acc[i + 2] += v.z; acc[i + 3] += v.w;
        }
    }
    float h[16];
#pragma unroll
    for (int idx = 0; idx < 16; idx++) {
        int br = idx >> 3, ch = idx & 7;
        float bias = (br ? ccb : cwb)[ch];
        float c0 = g_cwpb[br * 24 + ch * 3 + 0];
        float c1 = g_cwpb[br * 24 + ch * 3 + 1];
        float c2 = g_cwpb[br * 24 + ch * 3 + 2];
        bias += c0 + c1 + c2;
        if (l == 0) bias -= c0;
        if (l == NL - 1) bias -= c2;
        h[idx] = swishf(acc[idx] + bias);
    }
    __syncthreads();

    bool pad = (dur[b * NL + l] == 0.0f);
    float skv = g_sk[b * NL + l];
    float sdv = g_sd[b * NL + l];
    float E = pad ? 0.0f : (sdv - skv);
    float oms = pad ? 0.0f : (1.0f - skv);   // (t+1-sk) = t + oms
    float bzw[4];
#pragma unroll
    for (int q = 0; q < 4; q++) {
        float z = smwb[q] + oms * smw[q] + E * smw[4 + q];
#pragma unroll
        for (int ch = 0; ch < 8; ch++) z += (pad ? 0.0f : h[ch]) * smw[(2 + ch) * 4 + q];
        bzw[q] = z;
    }
    *(float4*)(g_bzw + (b * NL + l) * 4) = make_float4(bzw[0], bzw[1], bzw[2], bzw[3]);
    float bzc[2];
#pragma unroll
    for (int p = 0; p < 2; p++) {
        float z = smcb[p] + oms * smc[p] + E * smc[2 + p];
#pragma unroll
        for (int ch = 0; ch < 8; ch++) z += (pad ? 0.0f : h[8 + ch]) * smc[(2 + ch) * 2 + p];
        bzc[p] = z;
    }
    *(float2*)(g_bzc + (b * NL + l) * 2) = make_float2(bzc[0], bzc[1]);
    g_pad[b * NL + l] = pad ? 1.0f : 0.0f;
}

// ---------------- K4: M via tf32 MMA, output bf16x2-packed ----------------
__global__ __launch_bounds__(256) void k_mgemm2(const float* __restrict__ ph,
                                                const float* __restrict__ linw) {
    int b = blockIdx.z;
    int n0 = blockIdx.x * 128;
    int l0 = blockIdx.y * 128;
    int q = n0 >> 8;
    int o0 = n0 & 255;
    __shared__ __align__(16) float As[32][136];  // [k][l]
    __shared__ __align__(16) float Bs[32][136];  // [k][n]

    int tid = threadIdx.x;
    int wid = tid >> 5, lane = tid & 31;
    int warpRow = wid >> 1, warpCol = wid & 1;
    int g = lane >> 2, tg = lane & 3;
    const unsigned FULL = 0xffffffffu;

    const float* Ab = ph + (size_t)b * ND * NL;
    const float* Bb = linw + (size_t)q * 256 * 256;

    float acc[2][8][4];
#pragma unroll
    for (int mt = 0; mt < 2; mt++)
#pragma unroll
        for (int nt = 0; nt < 8; nt++)
#pragma unroll
            for (int j = 0; j < 4; j++) acc[mt][nt][j] = 0.0f;

    for (int k0 = 0; k0 < 256; k0 += 32) {
        __syncthreads();
#pragma unroll
        for (int i = 0; i < 4; i++) {
            int idx = i * 256 + tid;
            int r = idx >> 5, c4 = (idx & 31) * 4;
            float4 av = *(const float4*)(Ab + (size_t)(k0 + r) * NL + l0 + c4);
            As[r][c4 + 0] = to_tf32(av.x);
            As[r][c4 + 1] = to_tf32(av.y);
            As[r][c4 + 2] = to_tf32(av.z);
            As[r][c4 + 3] = to_tf32(av.w);
        }
#pragma unroll
        for (int i = 0; i < 4; i++) {
            int idx = i * 256 + tid;
            int r = idx >> 5, c4 = (idx & 31) * 4;
            float4 bv = *(const float4*)(Bb + (size_t)(k0 + r) * 256 + o0 + c4);
            Bs[r][c4 + 0] = to_tf32(bv.x);
            Bs[r][c4 + 1] = to_tf32(bv.y);
            Bs[r][c4 + 2] = to_tf32(bv.z);
            Bs[r][c4 + 3] = to_tf32(bv.w);
        }
        __syncthreads();
#pragma unroll
        for (int ks = 0; ks < 4; ks++) {
            int k = ks * 8;
            uint32_t af[2][4];
#pragma unroll
            for (int mt = 0; mt < 2; mt++) {
                int r0 = warpRow * 32 + mt * 16 + g;
                af[mt][0] = __float_as_uint(As[k + tg][r0]);
                af[mt][1] = __float_as_uint(As[k + tg][r0 + 8]);
                af[mt][2] = __float_as_uint(As[k + tg + 4][r0]);
                af[mt][3] = __float_as_uint(As[k + tg + 4][r0 + 8]);
            }
#pragma unroll
            for (int nt = 0; nt < 8; nt++) {
                int col = warpCol * 64 + nt * 8 + g;
                uint32_t b0 = __float_as_uint(Bs[k + tg][col]);
                uint32_t b1 = __float_as_uint(Bs[k + tg + 4][col]);
                mma_tf32(acc[0][nt], af[0][0], af[0][1], af[0][2], af[0][3], b0, b1);
                mma_tf32(acc[1][nt], af[1][0], af[1][1], af[1][2], af[1][3], b0, b1);
            }
        }
    }
    // epilogue: pack adjacent-l pairs (K order q-major: kk = q*128 + lglob/2)
    uint32_t* Mb = g_Mp + (size_t)b * 512 * 256;
#pragma unroll
    for (int mt = 0; mt < 2; mt++) {
        int lr0 = warpRow * 32 + mt * 16 + g;   // parity of lr0 == parity of g
#pragma unroll
        for (int nt = 0; nt < 8; nt++) {
            int nl = warpCol * 64 + nt * 8 + 2 * tg;
            float o00 = acc[mt][nt][0], o01 = acc[mt][nt][1];
            float o10 = acc[mt][nt][2], o11 = acc[mt][nt][3];
            float p00 = __shfl_down_sync(FULL, o00, 4);
            float p01 = __shfl_down_sync(FULL, o01, 4);
            float p10 = __shfl_down_sync(FULL, o10, 4);
            float p11 = __shfl_down_sync(FULL, o11, 4);
            if ((g & 1) == 0) {
                int kk0 = q * 128 + ((l0 + lr0) >> 1);
                int kk1 = kk0 + 4;   // lr1 = lr0 + 8
                Mb[(size_t)kk0 * 256 + o0 + nl]     = pack_bf16(o00, p00);
                Mb[(size_t)kk0 * 256 + o0 + nl + 1] = pack_bf16(o01, p01);
                Mb[(size_t)kk1 * 256 + o0 + nl]     = pack_bf16(o10, p10);
                Mb[(size_t)kk1 * 256 + o0 + nl + 1] = pack_bf16(o11, p11);
            }
        }
    }
}

// ---------------- K6: fused softmax-w + bf16 GEMM + wc epilogue -----------
// grid (1, 8, NB), 512 threads, BM=128 t-rows, BN=256, K=1024 (q*256+l)
#define SM_AS32  0                   // 128*20 u32 = 2560 words
#define SM_BS32  2560                // 16*264 u32 = 4224
#define SM_SC    6784                // 8*256      = 2048
#define SM_SB    8832                // 256
#define SM_SWC   9088                // 128*8      = 1024
#define SM_MX    10112               // 128*4      = 512
#define SM_RS    10624               // 128*4      = 512
#define SM_SW0   11136               // 4
#define SM_TOTF  11144

__global__ __launch_bounds__(512) void k_final2(
        const float* __restrict__ lwb, const float* __restrict__ lcW,
        const float* __restrict__ lcb, const float* __restrict__ mwW,
        const float* __restrict__ mcW, float* __restrict__ out) {
    extern __shared__ float sm[];
    uint32_t (*As32)[20]  = (uint32_t(*)[20])(sm + SM_AS32);
    uint32_t (*Bs32)[264] = (uint32_t(*)[264])(sm + SM_BS32);
    float (*sC)[256] = (float(*)[256])(sm + SM_SC);
    float* sB   = sm + SM_SB;
    float (*sWC)[8] = (float(*)[8])(sm + SM_SWC);
    float (*smx)[4] = (float(*)[4])(sm + SM_MX);
    float (*srs)[4] = (float(*)[4])(sm + SM_RS);
    float* sW0 = sm + SM_SW0;

    int b = blockIdx.z;
    int t0 = blockIdx.y * 128;
    int tid = threadIdx.x;
    int wid = tid >> 5, lane = tid & 31;
    int warpRow = wid >> 2, warpCol = wid & 3;
    int g = lane >> 2, tg = lane & 3;

    float W0[4] = {__ldg(mwW + 0), __ldg(mwW + 1), __ldg(mwW + 2), __ldg(mwW + 3)};
    float Wc0[2] = {__ldg(mcW + 0), __ldg(mcW + 1)};
    int flen = g_flen[b];
    const float* bzwb = g_bzw + b * NL * 4;
    const float* bzcb = g_bzc + b * NL * 2;
    const float* padb = g_pad + b * NL;
    const unsigned FULL = 0xffffffffu;

    // epilogue constants
    if (tid < 256) sB[tid] = lwb[tid] + lcb[tid];
    if (tid < 4) sW0[tid] = W0[tid];
    for (int i = tid; i < 8 * 256; i += 512)
        sC[i >> 8][i & 255] = lcW[i];

    // ---- prepass: per-row softmax stats + wc8 (warp wid owns rows 8w..8w+7)
#pragma unroll 1
    for (int rr = 0; rr < 8; rr++) {
        int r = wid * 8 + rr;
        int t = t0 + r;
        float tf = (float)t;
        if (t >= flen) {
            if (lane == 0) {
#pragma unroll
                for (int q = 0; q < 4; q++) { smx[r][q] = 0.0f; srs[r][q] = 0.0f; }
#pragma unroll
                for (int j = 0; j < 8; j++) sWC[r][j] = 0.0f;
            }
            continue;
        }
        float lg[8][4];
        float mx[4] = {-1e30f, -1e30f, -1e30f, -1e30f};
#pragma unroll
        for (int j = 0; j < 8; j++) {
            int l = j * 32 + lane;
            float4 bz = *(const float4*)(bzwb + l * 4);
            float pv = padb[l];
            float bza[4] = {bz.x, bz.y, bz.z, bz.w};
#pragma unroll
            for (int q = 0; q < 4; q++) {
                float s = swish_t(bza[q] + tf * W0[q]);
                lg[j][q] = (pv != 0.0f) ? -1e30f : s;
                mx[q] = fmaxf(mx[q], lg[j][q]);
            }
        }
#pragma unroll
        for (int off = 16; off > 0; off >>= 1)
#pragma unroll
            for (int q = 0; q < 4; q++)
                mx[q] = fmaxf(mx[q], __shfl_xor_sync(FULL, mx[q], off));
        float smv[4] = {0, 0, 0, 0};
#pragma unroll
        for (int j = 0; j < 8; j++)
#pragma unroll
            for (int q = 0; q < 4; q++) {
                float e = __expf(lg[j][q] - mx[q]);
                lg[j][q] = e;
                smv[q] += e;
            }
#pragma unroll
        for (int off = 16; off > 0; off >>= 1)
#pragma unroll
            for (int q = 0; q < 4; q++)
                smv[q] += __shfl_xor_sync(FULL, smv[q], off);
        float rs[4];
#pragma unroll
        for (int q = 0; q < 4; q++) rs[q] = __fdividef(1.0f, smv[q]);

        float wc[8] = {0, 0, 0, 0, 0, 0, 0, 0};
#pragma unroll
        for (int j = 0; j < 8; j++) {
            int l = j * 32 + lane;
            float2 bc = *(const float2*)(bzcb + l * 2);
            float cp0 = swish_t(bc.x + tf * Wc0[0]);
            float cp1 = swish_t(bc.y + tf * Wc0[1]);
#pragma unroll
            for (int q = 0; q < 4; q++) {
                float w = lg[j][q] * rs[q];
                wc[q * 2 + 0] += w * cp0;
                wc[q * 2 + 1] += w * cp1;
            }
        }
#pragma unroll
        for (int off = 16; off > 0; off >>= 1)
#pragma unroll
            for (int j = 0; j < 8; j++) wc[j] += __shfl_xor_sync(FULL, wc[j], off);
        if (lane == 0) {
#pragma unroll
            for (int q = 0; q < 4; q++) { smx[r][q] = mx[q]; srs[r][q] = rs[q]; }
#pragma unroll
            for (int j = 0; j < 8; j++) sWC[r][j] = wc[j];
        }
    }
    __syncthreads();

    // per-thread A coords: 2 rows, 4 k (one kk pair x2) per chunk
    int rA0 = tid >> 3, rA1 = 64 + (tid >> 3);
    int jA = tid & 7;                 // kk pair index within chunk
    float tfA0 = (float)(t0 + rA0), tfA1 = (float)(t0 + rA1);

    const uint32_t* Bb = g_Mp + (size_t)b * 512 * 256;
    int rB = tid >> 6, cB = (tid & 63) * 4;   // B load coords (i adds 8 rows)

    float acc[2][8][4];
#pragma unroll
    for (int mt = 0; mt < 2; mt++)
#pragma unroll
        for (int nt = 0; nt < 8; nt++)
#pragma unroll
            for (int j = 0; j < 4; j++) acc[mt][nt][j] = 0.0f;

    for (int k0 = 0; k0 < 1024; k0 += 32) {
        int q = k0 >> 8;
        __syncthreads();
        // A tile: compute w on the fly (4 consecutive l at fixed q)
        {
            int lb = (k0 & 255) + 4 * jA;
            float bz0 = bzwb[(lb + 0) * 4 + q];
            float bz1 = bzwb[(lb + 1) * 4 + q];
            float bz2 = bzwb[(lb + 2) * 4 + q];
            float bz3 = bzwb[(lb + 3) * 4 + q];
            float pv0 = padb[lb + 0], pv1 = padb[lb + 1];
            float pv2 = padb[lb + 2], pv3 = padb[lb + 3];
            float W0q = sW0[q];
            float mx0 = smx[rA0][q], rs0 = srs[rA0][q];
            float mx1 = smx[rA1][q], rs1 = srs[rA1][q];
            float ztA0 = tfA0 * W0q, ztA1 = tfA1 * W0q;

            float s00 = swish_t(bz0 + ztA0); s00 = (pv0 != 0.0f) ? -1e30f : s00;
            float s01 = swish_t(bz1 + ztA0); s01 = (pv1 != 0.0f) ? -1e30f : s01;
            float s02 = swish_t(bz2 + ztA0); s02 = (pv2 != 0.0f) ? -1e30f : s02;
            float s03 = swish_t(bz3 + ztA0); s03 = (pv3 != 0.0f) ? -1e30f : s03;
            float w00 = __expf(s00 - mx0) * rs0;
            float w01 = __expf(s01 - mx0) * rs0;
            float w02 = __expf(s02 - mx0) * rs0;
            float w03 = __expf(s03 - mx0) * rs0;
            As32[rA0][2 * jA + 0] = pack_bf16(w00, w01);
            As32[rA0][2 * jA + 1] = pack_bf16(w02, w03);

            float s10 = swish_t(bz0 + ztA1); s10 = (pv0 != 0.0f) ? -1e30f : s10;
            float s11 = swish_t(bz1 + ztA1); s11 = (pv1 != 0.0f) ? -1e30f : s11;
            float s12 = swish_t(bz2 + ztA1); s12 = (pv2 != 0.0f) ? -1e30f : s12;
            float s13 = swish_t(bz3 + ztA1); s13 = (pv3 != 0.0f) ? -1e30f : s13;
            float w10 = __expf(s10 - mx1) * rs1;
            float w11 = __expf(s11 - mx1) * rs1;
            float w12 = __expf(s12 - mx1) * rs1;
            float w13 = __expf(s13 - mx1) * rs1;
            As32[rA1][2 * jA + 0] = pack_bf16(w10, w11);
            As32[rA1][2 * jA + 1] = pack_bf16(w12, w13);
        }
        // B tile: 16 kk-rows x 256 cols of bf16x2
        {
            int kkb = k0 >> 1;
#pragma unroll
            for (int i = 0; i < 2; i++) {
                int r = i * 8 + rB;
                uint4 bv = *(const uint4*)(Bb + (size_t)(kkb + r) * 256 + cB);
                *(uint4*)(&Bs32[r][cB]) = bv;
            }
        }
        __syncthreads();
#pragma unroll
        for (int ks = 0; ks < 2; ks++) {
            int kc = ks * 8;
            uint32_t af[2][4];
#pragma unroll
            for (int mt = 0; mt < 2; mt++) {
                int r0 = warpRow * 32 + mt * 16 + g;
                af[mt][0] = As32[r0][kc + tg];
                af[mt][1] = As32[r0 + 8][kc + tg];
                af[mt][2] = As32[r0][kc + tg + 4];
                af[mt][3] = As32[r0 + 8][kc + tg + 4];
            }
#pragma unroll
            for (int nt = 0; nt < 8; nt++) {
                int col = warpCol * 64 + nt * 8 + g;
                uint32_t b0 = Bs32[kc + tg][col];
                uint32_t b1 = Bs32[kc + tg + 4][col];
                mma_bf16(acc[0][nt], af[0][0], af[0][1], af[0][2], af[0][3], b0, b1);
                mma_bf16(acc[1][nt], af[1][0], af[1][1], af[1][2], af[1][3], b0, b1);
            }
        }
    }

    // epilogue
#pragma unroll
    for (int mt = 0; mt < 2; mt++) {
        int lr0 = warpRow * 32 + mt * 16 + g;
        int lr1 = lr0 + 8;
        float wc0[8], wc1[8];
#pragma unroll
        for (int j = 0; j < 8; j++) { wc0[j] = sWC[lr0][j]; wc1[j] = sWC[lr1][j]; }
        int T0 = t0 + lr0, T1 = t0 + lr1;
#pragma unroll
        for (int nt = 0; nt < 8; nt++) {
            int nl = warpCol * 64 + nt * 8 + 2 * tg;
            float bias0 = sB[nl], bias1 = sB[nl + 1];
            float e00 = acc[mt][nt][0] + bias0, e01 = acc[mt][nt][1] + bias1;
            float e10 = acc[mt][nt][2] + bias0, e11 = acc[mt][nt][3] + bias1;
#pragma unroll
            for (int j = 0; j < 8; j++) {
                float c0v = sC[j][nl], c1v = sC[j][nl + 1];
                e00 += wc0[j] * c0v; e01 += wc0[j] * c1v;
                e10 += wc1[j] * c0v; e11 += wc1[j] * c1v;
            }
            if (T0 < NT)
                *(float2*)(out + ((size_t)(b * NT + T0)) * 256 + nl) = make_float2(e00, e01);
            if (T1 < NT)
                *(float2*)(out + ((size_t)(b * NT + T1)) * 256 + nl) = make_float2(e10, e11);
        }
    }
}

// ---------------------------------------------------------------------------
extern "C" void kernel_launch(void* const* d_in, const int* in_sizes, int n_in,
                              void* d_out, int out_size) {
    const float* durations = (const float*)d_in[0];
    const float* phoneme   = (const float*)d_in[1];
    // d_in[2] = phoneme_mask (unused; derived from durations == 0)
    const float* proj_w_W  = (const float*)d_in[3];
    const float* proj_w_b  = (const float*)d_in[4];
    const float* conv_w_W  = (const float*)d_in[5];
    const float* conv_w_b  = (const float*)d_in[6];
    const float* mlp_w_W   = (const float*)d_in[7];
    const float* mlp_w_b   = (const float*)d_in[8];
    const float* lin_w_W   = (const float*)d_in[9];
    const float* lin_w_b   = (const float*)d_in[10];
    const float* proj_c_W  = (const float*)d_in[11];
    const float* proj_c_b  = (const float*)d_in[12];
    const float* conv_c_W  = (const float*)d_in[13];
    const float* conv_c_b  = (const float*)d_in[14];
    const float* mlp_c_W   = (const float*)d_in[15];
    const float* mlp_c_b   = (const float*)d_in[16];
    const float* lin_c_W   = (const float*)d_in[17];
    const float* lin_c_b   = (const float*)d_in[18];
    float* out = (float*)d_out;

    static int smset = 0;
    if (!smset) {
        cudaFuncSetAttribute(k_final2, cudaFuncAttributeMaxDynamicSharedMemorySize,
                             SM_TOTF * sizeof(float));
        smset = 1;
    }

    k_scan<<<NB, NL>>>(durations);
    k_weff<<<dim3(3, 8, 2), ND>>>(proj_w_W, conv_w_W, proj_c_W, conv_c_W);
    k_cwpb<<<1, 64>>>(conv_w_W, proj_w_b, conv_c_W, proj_c_b);
    k_conv_part<<<dim3(NB, 32), NL>>>(phoneme);
    k_conv_fin<<<NB, NL>>>(durations, conv_w_b, conv_c_b,
                           mlp_w_W, mlp_w_b, mlp_c_W, mlp_c_b);
    k_mgemm2<<<dim3(8, 2, NB), 256>>>(phoneme, lin_w_W);
    k_final2<<<dim3(1, 8, NB), 512, SM_TOTF * sizeof(float)>>>(
        lin_w_b, lin_c_W, lin_c_b, mlp_w_W, mlp_c_W, out);
}

// round 15
// speedup vs baseline: 1.3444x; 1.3444x over previous
#include <cuda_runtime.h>
#include <cuda_bf16.h>
#include <math.h>
#include <stdint.h>

#define NB 16
#define ND 256
#define NL 256
#define NT 1000
#define NCH 8
#define NDW 4
#define NDC 2

// ---------------- scratch (device globals; no allocations allowed) ----------
__device__ __align__(16) float g_sd[NB * NL];
__device__ __align__(16) float g_sk[NB * NL];
__device__ int g_flen[NB];
__device__ __align__(16) float g_weff[ND * 48];       // [d][br*8+ch][k]
__device__ __align__(16) float g_cwpb[48];            // [br][ch][k]
__device__ __align__(16) float g_hpart[32 * NB * NL * 16]; // [chunk][(b*L+l)*16+idx]
__device__ __align__(16) float g_bzw[NB * NL * 4];    // t-invariant w-logit base
__device__ __align__(16) float g_bzc[NB * NL * 2];    // t-invariant c base
__device__ __align__(16) float g_pad[NB * NL];        // 1.0 if phone_pad
__device__ __align__(16) float g_M[(size_t)NB * 1024 * 256];   // [b][l*4+q][o]  (tf32)

__device__ __forceinline__ float swishf(float z) {
    return z / (1.0f + expf(-z));
}
__device__ __forceinline__ float tanh_approx(float x) {
    float y; asm("tanh.approx.f32 %0, %1;" : "=f"(y) : "f"(x)); return y;
}
__device__ __forceinline__ float swish_t(float z) {
    return z * (0.5f + 0.5f * tanh_approx(0.5f * z));
}
__device__ __forceinline__ float to_tf32(float x) {
    uint32_t u;
    asm("cvt.rna.tf32.f32 %0, %1;" : "=r"(u) : "f"(x));
    return __uint_as_float(u);
}
__device__ __forceinline__ void mma_tf32(float c[4], uint32_t a0, uint32_t a1,
                                         uint32_t a2, uint32_t a3,
                                         uint32_t b0, uint32_t b1) {
    asm volatile(
        "mma.sync.aligned.m16n8k8.row.col.f32.tf32.tf32.f32 "
        "{%0,%1,%2,%3}, {%4,%5,%6,%7}, {%8,%9}, {%0,%1,%2,%3};\n"
        : "+f"(c[0]), "+f"(c[1]), "+f"(c[2]), "+f"(c[3])
        : "r"(a0), "r"(a1), "r"(a2), "r"(a3), "r"(b0), "r"(b1));
}

// ---------------- K1: cumsum scan, frame_len ------------------------------
__global__ void k_scan(const float* __restrict__ dur) {
    int b = blockIdx.x, l = threadIdx.x;
    __shared__ float s[NL];
    float x = dur[b * NL + l];
    s[l] = x;
    __syncthreads();
#pragma unroll
    for (int off = 1; off < NL; off <<= 1) {
        float v = (l >= off) ? s[l - off] : 0.0f;
        __syncthreads();
        s[l] += v;
        __syncthreads();
    }
    float sd = s[l];
    g_sd[b * NL + l] = sd;
    g_sk[b * NL + l] = sd - x;
    if (l == 0) {
        float tot = s[NL - 1];
        int fl = (int)rintf(tot);
        if (fl < 0) fl = 0;
        if (fl > NT) fl = NT;
        g_flen[b] = fl;
    }
}

// ---------------- K2: fold projection into conv weights -------------------
__global__ void k_weff(const float* __restrict__ pwW, const float* __restrict__ cwW,
                       const float* __restrict__ pcW, const float* __restrict__ ccW) {
    int k = blockIdx.x, ch = blockIdx.y, br = blockIdx.z, d = threadIdx.x;
    const float* cw = br ? ccW : cwW;
    const float* pw = br ? pcW : pwW;
    float acc = 0.0f;
#pragma unroll 4
    for (int o = 0; o < ND; o++)
        acc += cw[(ch * ND + o) * 3 + k] * pw[o * ND + d];
    g_weff[d * 48 + (br * 8 + ch) * 3 + k] = acc;
}

__global__ void k_cwpb(const float* __restrict__ cwW, const float* __restrict__ pwb,
                       const float* __restrict__ ccW, const float* __restrict__ pcb) {
    int i = threadIdx.x;
    if (i >= 48) return;
    int br = i / 24, rem = i % 24, ch = rem / 3, k = rem % 3;
    const float* cw = br ? ccW : cwW;
    const float* pb = br ? pcb : pwb;
    float a = 0.0f;
    for (int o = 0; o < ND; o++) a += cw[(ch * ND + o) * 3 + k] * pb[o];
    g_cwpb[i] = a;
}

// ---------------- K3a: partial conv over 8-d chunks -----------------------
__global__ void k_conv_part(const float* __restrict__ ph) {
    int b = blockIdx.x, c = blockIdx.y, l = threadIdx.x;
    __shared__ __align__(16) float sWe[8 * 48];
    for (int i = l; i < 8 * 48; i += NL) sWe[i] = g_weff[c * 8 * 48 + i];
    __syncthreads();

    const float* phb = ph + (size_t)b * ND * NL + (size_t)(c * 8) * NL;
    float acc[16];
#pragma unroll
    for (int i = 0; i < 16; i++) acc[i] = 0.0f;

#pragma unroll
    for (int dd = 0; dd < 8; dd++) {
        float vm = (l > 0) ? phb[dd * NL + l - 1] : 0.0f;
        float v0 = phb[dd * NL + l];
        float vp = (l < NL - 1) ? phb[dd * NL + l + 1] : 0.0f;
        float v[3] = {vm, v0, vp};
        const float* wd = sWe + dd * 48;
#pragma unroll
        for (int lin = 0; lin < 48; lin += 4) {
            float4 w = *(const float4*)(wd + lin);
            acc[(lin + 0) / 3] += w.x * v[(lin + 0) % 3];
            acc[(lin + 1) / 3] += w.y * v[(lin + 1) % 3];
            acc[(lin + 2) / 3] += w.z * v[(lin + 2) % 3];
            acc[(lin + 3) / 3] += w.w * v[(lin + 3) % 3];
        }
    }
    float* outp = g_hpart + ((size_t)(c * NB + b) * NL + l) * 16;
#pragma unroll
    for (int i = 0; i < 16; i += 4)
        *(float4*)(outp + i) = make_float4(acc[i], acc[i + 1], acc[i + 2], acc[i + 3]);
}

// ---- K3b: reduce partials + bias + swish, fold h into t-invariant bases --
__global__ void k_conv_fin(const float* __restrict__ dur,
                           const float* __restrict__ cwb, const float* __restrict__ ccb,
                           const float* __restrict__ mwW, const float* __restrict__ mwb,
                           const float* __restrict__ mcW, const float* __restrict__ mcb) {
    int b = blockIdx.x, l = threadIdx.x;
    __shared__ float smw[40], smwb[4], smc[20], smcb[2];
    if (l < 40) smw[l] = mwW[l];
    if (l < 4) smwb[l] = mwb[l];
    if (l >= 64 && l < 84) smc[l - 64] = mcW[l - 64];
    if (l >= 96 && l < 98) smcb[l - 96] = mcb[l - 96];

    float acc[16];
#pragma unroll
    for (int i = 0; i < 16; i++) acc[i] = 0.0f;
#pragma unroll
    for (int c = 0; c < 32; c++) {
        const float* p = g_hpart + ((size_t)(c * NB + b) * NL + l) * 16;
#pragma unroll
        for (int i = 0; i < 16; i += 4) {
            float4 v = *(const float4*)(p + i);
            acc[i] += v.x; acc[i + 1] += v.y; acc[i + 2] += v.z; acc[i + 3] += v.w;
        }
    }
    float h[16];
#pragma unroll
    for (int idx = 0; idx < 16; idx++) {
        int br = idx >> 3, ch = idx & 7;
        float bias = (br ? ccb : cwb)[ch];
        float c0 = g_cwpb[br * 24 + ch * 3 + 0];
        float c1 = g_cwpb[br * 24 + ch * 3 + 1];
        float c2 = g_cwpb[br * 24 + ch * 3 + 2];
        bias += c0 + c1 + c2;
        if (l == 0) bias -= c0;
        if (l == NL - 1) bias -= c2;
        h[idx] = swishf(acc[idx] + bias);
    }
    __syncthreads();

    bool pad = (dur[b * NL + l] == 0.0f);
    float skv = g_sk[b * NL + l];
    float sdv = g_sd[b * NL + l];
    float E = pad ? 0.0f : (sdv - skv);
    float oms = pad ? 0.0f : (1.0f - skv);   // (t+1-sk) = t + oms
    float bzw[4];
#pragma unroll
    for (int q = 0; q < 4; q++) {
        float z = smwb[q] + oms * smw[q] + E * smw[4 + q];
#pragma unroll
        for (int ch = 0; ch < 8; ch++) z += (pad ? 0.0f : h[ch]) * smw[(2 + ch) * 4 + q];
        bzw[q] = z;
    }
    *(float4*)(g_bzw + (b * NL + l) * 4) = make_float4(bzw[0], bzw[1], bzw[2], bzw[3]);
    float bzc[2];
#pragma unroll
    for (int p = 0; p < 2; p++) {
        float z = smcb[p] + oms * smc[p] + E * smc[2 + p];
#pragma unroll
        for (int ch = 0; ch < 8; ch++) z += (pad ? 0.0f : h[8 + ch]) * smc[(2 + ch) * 2 + p];
        bzc[p] = z;
    }
    *(float2*)(g_bzc + (b * NL + l) * 2) = make_float2(bzc[0], bzc[1]);
    g_pad[b * NL + l] = pad ? 1.0f : 0.0f;
}

// ---------------- K4: M via tf32 MMA (R7 structure) -----------------------
__global__ __launch_bounds__(256) void k_mgemm2(const float* __restrict__ ph,
                                                const float* __restrict__ linw) {
    int b = blockIdx.z;
    int n0 = blockIdx.x * 128;
    int l0 = blockIdx.y * 128;
    int q = n0 >> 8;
    int o0 = n0 & 255;
    __shared__ __align__(16) float As[32][136];  // [k][l]
    __shared__ __align__(16) float Bs[32][136];  // [k][n]

    int tid = threadIdx.x;
    int wid = tid >> 5, lane = tid & 31;
    int warpRow = wid >> 1, warpCol = wid & 1;
    int g = lane >> 2, tg = lane & 3;

    const float* Ab = ph + (size_t)b * ND * NL;
    const float* Bb = linw + (size_t)q * 256 * 256;

    float acc[2][8][4];
#pragma unroll
    for (int mt = 0; mt < 2; mt++)
#pragma unroll
        for (int nt = 0; nt < 8; nt++)
#pragma unroll
            for (int j = 0; j < 4; j++) acc[mt][nt][j] = 0.0f;

    for (int k0 = 0; k0 < 256; k0 += 32) {
        __syncthreads();
#pragma unroll
        for (int i = 0; i < 4; i++) {
            int idx = i * 256 + tid;
            int r = idx >> 5, c4 = (idx & 31) * 4;
            float4 av = *(const float4*)(Ab + (size_t)(k0 + r) * NL + l0 + c4);
            As[r][c4 + 0] = to_tf32(av.x);
            As[r][c4 + 1] = to_tf32(av.y);
            As[r][c4 + 2] = to_tf32(av.z);
            As[r][c4 + 3] = to_tf32(av.w);
        }
#pragma unroll
        for (int i = 0; i < 4; i++) {
            int idx = i * 256 + tid;
            int r = idx >> 5, c4 = (idx & 31) * 4;
            float4 bv = *(const float4*)(Bb + (size_t)(k0 + r) * 256 + o0 + c4);
            Bs[r][c4 + 0] = to_tf32(bv.x);
            Bs[r][c4 + 1] = to_tf32(bv.y);
            Bs[r][c4 + 2] = to_tf32(bv.z);
            Bs[r][c4 + 3] = to_tf32(bv.w);
        }
        __syncthreads();
#pragma unroll
        for (int ks = 0; ks < 4; ks++) {
            int k = ks * 8;
            uint32_t af[2][4];
#pragma unroll
            for (int mt = 0; mt < 2; mt++) {
                int r0 = warpRow * 32 + mt * 16 + g;
                af[mt][0] = __float_as_uint(As[k + tg][r0]);
                af[mt][1] = __float_as_uint(As[k + tg][r0 + 8]);
                af[mt][2] = __float_as_uint(As[k + tg + 4][r0]);
                af[mt][3] = __float_as_uint(As[k + tg + 4][r0 + 8]);
            }
#pragma unroll
            for (int nt = 0; nt < 8; nt++) {
                int col = warpCol * 64 + nt * 8 + g;
                uint32_t b0 = __float_as_uint(Bs[k + tg][col]);
                uint32_t b1 = __float_as_uint(Bs[k + tg + 4][col]);
                mma_tf32(acc[0][nt], af[0][0], af[0][1], af[0][2], af[0][3], b0, b1);
                mma_tf32(acc[1][nt], af[1][0], af[1][1], af[1][2], af[1][3], b0, b1);
            }
        }
    }
    float* Mb = g_M + (size_t)b * 1024 * 256;
#pragma unroll
    for (int mt = 0; mt < 2; mt++) {
        int lr0 = warpRow * 32 + mt * 16 + g;
        int lr1 = lr0 + 8;
        int row0 = (l0 + lr0) * 4 + q;
        int row1 = (l0 + lr1) * 4 + q;
#pragma unroll
        for (int nt = 0; nt < 8; nt++) {
            int nl = warpCol * 64 + nt * 8 + 2 * tg;
            *(float2*)(Mb + (size_t)row0 * 256 + o0 + nl) =
                make_float2(to_tf32(acc[mt][nt][0]), to_tf32(acc[mt][nt][1]));
            *(float2*)(Mb + (size_t)row1 * 256 + o0 + nl) =
                make_float2(to_tf32(acc[mt][nt][2]), to_tf32(acc[mt][nt][3]));
        }
    }
}

// ---------------- K6: fused softmax-w + tf32 GEMM + wc epilogue -----------
// grid (1, 8, NB), 512 threads, BM=128 t-rows, BN=256, K=1024 (l*4+q)
// double-buffered As/Bs: one __syncthreads per K-chunk
#define SM_AS    0                  // 2 * 128*36 = 9216 floats
#define SM_BS    9216               // 2 * 32*264 = 16896
#define SM_SC    26112              // 8*256      = 2048
#define SM_SB    28160              // 256
#define SM_SWC   28416              // 128*8      = 1024
#define SM_MX    29440              // 128*4      = 512
#define SM_RS    29952              // 128*4      = 512
#define SM_TOTF  30464

__global__ __launch_bounds__(512) void k_final2(
        const float* __restrict__ lwb, const float* __restrict__ lcW,
        const float* __restrict__ lcb, const float* __restrict__ mwW,
        const float* __restrict__ mcW, float* __restrict__ out) {
    extern __shared__ float sm[];
    float (*sC)[256] = (float(*)[256])(sm + SM_SC);
    float* sB   = sm + SM_SB;
    float (*sWC)[8] = (float(*)[8])(sm + SM_SWC);
    float (*smx)[4] = (float(*)[4])(sm + SM_MX);
    float (*srs)[4] = (float(*)[4])(sm + SM_RS);

    int b = blockIdx.z;
    int t0 = blockIdx.y * 128;
    int tid = threadIdx.x;
    int wid = tid >> 5, lane = tid & 31;
    int warpRow = wid >> 2, warpCol = wid & 3;
    int g = lane >> 2, tg = lane & 3;

    float W0[4] = {__ldg(mwW + 0), __ldg(mwW + 1), __ldg(mwW + 2), __ldg(mwW + 3)};
    float Wc0[2] = {__ldg(mcW + 0), __ldg(mcW + 1)};
    int flen = g_flen[b];
    const float* bzwb = g_bzw + b * NL * 4;
    const float* bzcb = g_bzc + b * NL * 2;
    const float* padb = g_pad + b * NL;
    const unsigned FULL = 0xffffffffu;

    // epilogue constants
    if (tid < 256) sB[tid] = lwb[tid] + lcb[tid];
    for (int i = tid; i < 8 * 256; i += 512)
        sC[i >> 8][i & 255] = lcW[i];

    // ---- prepass: per-row softmax stats + wc8 (warp wid owns rows 8w..8w+7)
#pragma unroll 1
    for (int rr = 0; rr < 8; rr++) {
        int r = wid * 8 + rr;
        int t = t0 + r;
        float tf = (float)t;
        if (t >= flen) {
            if (lane == 0) {
#pragma unroll
                for (int q = 0; q < 4; q++) { smx[r][q] = 0.0f; srs[r][q] = 0.0f; }
#pragma unroll
                for (int j = 0; j < 8; j++) sWC[r][j] = 0.0f;
            }
            continue;
        }
        float lg[8][4];
        float mx[4] = {-1e30f, -1e30f, -1e30f, -1e30f};
#pragma unroll
        for (int j = 0; j < 8; j++) {
            int l = j * 32 + lane;
            float4 bz = *(const float4*)(bzwb + l * 4);
            float pv = padb[l];
            float bza[4] = {bz.x, bz.y, bz.z, bz.w};
#pragma unroll
            for (int q = 0; q < 4; q++) {
                float s = swish_t(bza[q] + tf * W0[q]);
                lg[j][q] = (pv != 0.0f) ? -1e30f : s;
                mx[q] = fmaxf(mx[q], lg[j][q]);
            }
        }
#pragma unroll
        for (int off = 16; off > 0; off >>= 1)
#pragma unroll
            for (int q = 0; q < 4; q++)
                mx[q] = fmaxf(mx[q], __shfl_xor_sync(FULL, mx[q], off));
        float smv[4] = {0, 0, 0, 0};
#pragma unroll
        for (int j = 0; j < 8; j++)
#pragma unroll
            for (int q = 0; q < 4; q++) {
                float e = __expf(lg[j][q] - mx[q]);
                lg[j][q] = e;
                smv[q] += e;
            }
#pragma unroll
        for (int off = 16; off > 0; off >>= 1)
#pragma unroll
            for (int q = 0; q < 4; q++)
                smv[q] += __shfl_xor_sync(FULL, smv[q], off);
        float rs[4];
#pragma unroll
        for (int q = 0; q < 4; q++) rs[q] = __fdividef(1.0f, smv[q]);

        float wc[8] = {0, 0, 0, 0, 0, 0, 0, 0};
#pragma unroll
        for (int j = 0; j < 8; j++) {
            int l = j * 32 + lane;
            float2 bc = *(const float2*)(bzcb + l * 2);
            float cp0 = swish_t(bc.x + tf * Wc0[0]);
            float cp1 = swish_t(bc.y + tf * Wc0[1]);
#pragma unroll
            for (int q = 0; q < 4; q++) {
                float w = lg[j][q] * rs[q];
                wc[q * 2 + 0] += w * cp0;
                wc[q * 2 + 1] += w * cp1;
            }
        }
#pragma unroll
        for (int off = 16; off > 0; off >>= 1)
#pragma unroll
            for (int j = 0; j < 8; j++) wc[j] += __shfl_xor_sync(FULL, wc[j], off);
        if (lane == 0) {
#pragma unroll
            for (int q = 0; q < 4; q++) { smx[r][q] = mx[q]; srs[r][q] = rs[q]; }
#pragma unroll
            for (int j = 0; j < 8; j++) sWC[r][j] = wc[j];
        }
    }
    __syncthreads();

    // per-thread A-row constants (2 slots)
    int rA0 = tid >> 3, rA1 = 64 + (tid >> 3);
    int cA4 = (tid & 7) * 4;
    float tfA0 = (float)(t0 + rA0), tfA1 = (float)(t0 + rA1);
    float mxA0[4], rsA0[4], mxA1[4], rsA1[4];
#pragma unroll
    for (int q = 0; q < 4; q++) {
        mxA0[q] = smx[rA0][q]; rsA0[q] = srs[rA0][q];
        mxA1[q] = smx[rA1][q]; rsA1[q] = srs[rA1][q];
    }

    const float* Bb = g_M + (size_t)b * 1024 * 256;

    float acc[2][8][4];
#pragma unroll
    for (int mt = 0; mt < 2; mt++)
#pragma unroll
        for (int nt = 0; nt < 8; nt++)
#pragma unroll
            for (int j = 0; j < 4; j++) acc[mt][nt][j] = 0.0f;

    // fill lambda: A compute + B load into buffer `buf` for chunk k0
    auto fillA = [&](int buf, int k0) {
        float (*As)[36] = (float(*)[36])(sm + SM_AS + buf * 4608);
        int l = (k0 + cA4) >> 2;
        float4 bz = *(const float4*)(bzwb + l * 4);
        float pv = padb[l];
        float bza[4] = {bz.x, bz.y, bz.z, bz.w};
        float w0[4], w1[4];
#pragma unroll
        for (int q = 0; q < 4; q++) {
            float s0 = swish_t(bza[q] + tfA0 * W0[q]);
            s0 = (pv != 0.0f) ? -1e30f : s0;
            w0[q] = __expf(s0 - mxA0[q]) * rsA0[q];
            float s1 = swish_t(bza[q] + tfA1 * W0[q]);
            s1 = (pv != 0.0f) ? -1e30f : s1;
            w1[q] = __expf(s1 - mxA1[q]) * rsA1[q];
        }
        *(float4*)(&As[rA0][cA4]) = make_float4(to_tf32(w0[0]), to_tf32(w0[1]),
                                                to_tf32(w0[2]), to_tf32(w0[3]));
        *(float4*)(&As[rA1][cA4]) = make_float4(to_tf32(w1[0]), to_tf32(w1[1]),
                                                to_tf32(w1[2]), to_tf32(w1[3]));
    };
    auto fillB = [&](int buf, int k0) {
        float (*Bs)[264] = (float(*)[264])(sm + SM_BS + buf * 8448);
#pragma unroll
        for (int i = 0; i < 4; i++) {
            int idx = i * 512 + tid;
            int r = idx >> 6, c4 = (idx & 63) * 4;
            float4 bv = *(const float4*)(Bb + (size_t)(k0 + r) * 256 + c4);
            *(float4*)(&Bs[r][c4]) = bv;
        }
    };

    // prologue: fill buffer 0 with chunk 0
    fillA(0, 0);
    fillB(0, 0);
    __syncthreads();

    int cur = 0;
    for (int k0 = 0; k0 < 1024; k0 += 32) {
        int nxt = cur ^ 1;
        if (k0 + 32 < 1024) {
            fillA(nxt, k0 + 32);
            fillB(nxt, k0 + 32);
        }
        float (*As)[36]  = (float(*)[36])(sm + SM_AS + cur * 4608);
        float (*Bs)[264] = (float(*)[264])(sm + SM_BS + cur * 8448);
#pragma unroll
        for (int ks = 0; ks < 4; ks++) {
            int k = ks * 8;
            uint32_t af[2][4];
#pragma unroll
            for (int mt = 0; mt < 2; mt++) {
                int r0 = warpRow * 32 + mt * 16 + g;
                af[mt][0] = __float_as_uint(As[r0][k + tg]);
                af[mt][1] = __float_as_uint(As[r0 + 8][k + tg]);
                af[mt][2] = __float_as_uint(As[r0][k + tg + 4]);
                af[mt][3] = __float_as_uint(As[r0 + 8][k + tg + 4]);
            }
#pragma unroll
            for (int nt = 0; nt < 8; nt++) {
                int col = warpCol * 64 + nt * 8 + g;
                uint32_t b0 = __float_as_uint(Bs[k + tg][col]);
                uint32_t b1 = __float_as_uint(Bs[k + tg + 4][col]);
                mma_tf32(acc[0][nt], af[0][0], af[0][1], af[0][2], af[0][3], b0, b1);
                mma_tf32(acc[1][nt], af[1][0], af[1][1], af[1][2], af[1][3], b0, b1);
            }
        }
        __syncthreads();   // next buffer filled AND current reads done
        cur = nxt;
    }

    // epilogue
#pragma unroll
    for (int mt = 0; mt < 2; mt++) {
        int lr0 = warpRow * 32 + mt * 16 + g;
        int lr1 = lr0 + 8;
        float wc0[8], wc1[8];
#pragma unroll
        for (int j = 0; j < 8; j++) { wc0[j] = sWC[lr0][j]; wc1[j] = sWC[lr1][j]; }
        int T0 = t0 + lr0, T1 = t0 + lr1;
#pragma unroll
        for (int nt = 0; nt < 8; nt++) {
            int nl = warpCol * 64 + nt * 8 + 2 * tg;
            float bias0 = sB[nl], bias1 = sB[nl + 1];
            float e00 = acc[mt][nt][0] + bias0, e01 = acc[mt][nt][1] + bias1;
            float e10 = acc[mt][nt][2] + bias0, e11 = acc[mt][nt][3] + bias1;
#pragma unroll
            for (int j = 0; j < 8; j++) {
                float c0v = sC[j][nl], c1v = sC[j][nl + 1];
                e00 += wc0[j] * c0v; e01 += wc0[j] * c1v;
                e10 += wc1[j] * c0v; e11 += wc1[j] * c1v;
            }
            if (T0 < NT)
                *(float2*)(out + ((size_t)(b * NT + T0)) * 256 + nl) = make_float2(e00, e01);
            if (T1 < NT)
                *(float2*)(out + ((size_t)(b * NT + T1)) * 256 + nl) = make_float2(e10, e11);
        }
    }
}

// ---------------------------------------------------------------------------
extern "C" void kernel_launch(void* const* d_in, const int* in_sizes, int n_in,
                              void* d_out, int out_size) {
    const float* durations = (const float*)d_in[0];
    const float* phoneme   = (const float*)d_in[1];
    // d_in[2] = phoneme_mask (unused; derived from durations == 0)
    const float* proj_w_W  = (const float*)d_in[3];
    const float* proj_w_b  = (const float*)d_in[4];
    const float* conv_w_W  = (const float*)d_in[5];
    const float* conv_w_b  = (const float*)d_in[6];
    const float* mlp_w_W   = (const float*)d_in[7];
    const float* mlp_w_b   = (const float*)d_in[8];
    const float* lin_w_W   = (const float*)d_in[9];
    const float* lin_w_b   = (const float*)d_in[10];
    const float* proj_c_W  = (const float*)d_in[11];
    const float* proj_c_b  = (const float*)d_in[12];
    const float* conv_c_W  = (const float*)d_in[13];
    const float* conv_c_b  = (const float*)d_in[14];
    const float* mlp_c_W   = (const float*)d_in[15];
    const float* mlp_c_b   = (const float*)d_in[16];
    const float* lin_c_W   = (const float*)d_in[17];
    const float* lin_c_b   = (const float*)d_in[18];
    float* out = (float*)d_out;

    static int smset = 0;
    if (!smset) {
        cudaFuncSetAttribute(k_final2, cudaFuncAttributeMaxDynamicSharedMemorySize,
                             SM_TOTF * sizeof(float));
        smset = 1;
    }

    k_scan<<<NB, NL>>>(durations);
    k_weff<<<dim3(3, 8, 2), ND>>>(proj_w_W, conv_w_W, proj_c_W, conv_c_W);
    k_cwpb<<<1, 64>>>(conv_w_W, proj_w_b, conv_c_W, proj_c_b);
    k_conv_part<<<dim3(NB, 32), NL>>>(phoneme);
    k_conv_fin<<<NB, NL>>>(durations, conv_w_b, conv_c_b,
                           mlp_w_W, mlp_w_b, mlp_c_W, mlp_c_b);
    k_mgemm2<<<dim3(8, 2, NB), 256>>>(phoneme, lin_w_W);
    k_final2<<<dim3(1, 8, NB), 512, SM_TOTF * sizeof(float)>>>(
        lin_w_b, lin_c_W, lin_c_b, mlp_w_W, mlp_c_W, out);
}

// round 17
// speedup vs baseline: 1.4798x; 1.1007x over previous
#include <cuda_runtime.h>
#include <cuda_bf16.h>
#include <math.h>
#include <stdint.h>

#define NB 16
#define ND 256
#define NL 256
#define NT 1000
#define NCH 8
#define NDW 4
#define NDC 2

// ---------------- scratch (device globals; no allocations allowed) ----------
__device__ __align__(16) float g_sd[NB * NL];
__device__ __align__(16) float g_sk[NB * NL];
__device__ int g_flen[NB];
__device__ __align__(16) float g_weff[ND * 48];       // [d][br*8+ch][k]
__device__ __align__(16) float g_cwpb[48];            // [br][ch][k]
__device__ __align__(16) float g_hpart[32 * NB * NL * 16]; // [chunk][(b*L+l)*16+idx]
__device__ __align__(16) float g_bzw[NB * NL * 4];    // t-invariant w-logit base
__device__ __align__(16) float g_bzc[NB * NL * 2];    // t-invariant c base
__device__ __align__(16) float g_pad[NB * NL];        // 1.0 if phone_pad
__device__ __align__(16) float g_M[(size_t)NB * 1024 * 256];   // [b][l*4+q][o]  (tf32)

__device__ __forceinline__ float swishf(float z) {
    return z / (1.0f + expf(-z));
}
__device__ __forceinline__ float tanh_approx(float x) {
    float y; asm("tanh.approx.f32 %0, %1;" : "=f"(y) : "f"(x)); return y;
}
__device__ __forceinline__ float swish_t(float z) {
    return z * (0.5f + 0.5f * tanh_approx(0.5f * z));
}
__device__ __forceinline__ float to_tf32(float x) {
    uint32_t u;
    asm("cvt.rna.tf32.f32 %0, %1;" : "=r"(u) : "f"(x));
    return __uint_as_float(u);
}
__device__ __forceinline__ void cp_async16(uint32_t saddr, const void* gptr) {
    asm volatile("cp.async.cg.shared.global [%0], [%1], 16;"
                 :: "r"(saddr), "l"(gptr));
}
__device__ __forceinline__ void cp_commit() {
    asm volatile("cp.async.commit_group;");
}
__device__ __forceinline__ void cp_wait0() {
    asm volatile("cp.async.wait_group 0;");
}
__device__ __forceinline__ void mma_tf32(float c[4], uint32_t a0, uint32_t a1,
                                         uint32_t a2, uint32_t a3,
                                         uint32_t b0, uint32_t b1) {
    asm volatile(
        "mma.sync.aligned.m16n8k8.row.col.f32.tf32.tf32.f32 "
        "{%0,%1,%2,%3}, {%4,%5,%6,%7}, {%8,%9}, {%0,%1,%2,%3};\n"
        : "+f"(c[0]), "+f"(c[1]), "+f"(c[2]), "+f"(c[3])
        : "r"(a0), "r"(a1), "r"(a2), "r"(a3), "r"(b0), "r"(b1));
}

// ---------------- K1: cumsum scan, frame_len ------------------------------
__global__ void k_scan(const float* __restrict__ dur) {
    int b = blockIdx.x, l = threadIdx.x;
    __shared__ float s[NL];
    float x = dur[b * NL + l];
    s[l] = x;
    __syncthreads();
#pragma unroll
    for (int off = 1; off < NL; off <<= 1) {
        float v = (l >= off) ? s[l - off] : 0.0f;
        __syncthreads();
        s[l] += v;
        __syncthreads();
    }
    float sd = s[l];
    g_sd[b * NL + l] = sd;
    g_sk[b * NL + l] = sd - x;
    if (l == 0) {
        float tot = s[NL - 1];
        int fl = (int)rintf(tot);
        if (fl < 0) fl = 0;
        if (fl > NT) fl = NT;
        g_flen[b] = fl;
    }
}

// ---------------- K2: fold projection into conv weights (+cwpb) -----------
__global__ void k_weff(const float* __restrict__ pwW, const float* __restrict__ cwW,
                       const float* __restrict__ pcW, const float* __restrict__ ccW,
                       const float* __restrict__ pwb, const float* __restrict__ pcb) {
    int k = blockIdx.x, ch = blockIdx.y, br = blockIdx.z, d = threadIdx.x;
    const float* cw = br ? ccW : cwW;
    const float* pw = br ? pcW : pwW;
    float acc = 0.0f;
#pragma unroll 4
    for (int o = 0; o < ND; o++)
        acc += cw[(ch * ND + o) * 3 + k] * pw[o * ND + d];
    g_weff[d * 48 + (br * 8 + ch) * 3 + k] = acc;

    // fold biases once (block (0,0,0), first 48 threads)
    if (k == 0 && ch == 0 && br == 0 && d < 48) {
        int br2 = d / 24, rem = d % 24, ch2 = rem / 3, k2 = rem % 3;
        const float* cw2 = br2 ? ccW : cwW;
        const float* pb2 = br2 ? pcb : pwb;
        float a = 0.0f;
        for (int o = 0; o < ND; o++) a += cw2[(ch2 * ND + o) * 3 + k2] * pb2[o];
        g_cwpb[d] = a;
    }
}

// ---------------- K3a: partial conv over 8-d chunks (smem tile) -----------
__global__ void k_conv_part(const float* __restrict__ ph) {
    int b = blockIdx.x, c = blockIdx.y, l = threadIdx.x;
    __shared__ __align__(16) float sWe[8 * 48];
    __shared__ float sph[8][NL + 2];
    for (int i = l; i < 8 * 48; i += NL) sWe[i] = g_weff[c * 8 * 48 + i];

    const float* phb = ph + (size_t)b * ND * NL + (size_t)(c * 8) * NL;
#pragma unroll
    for (int dd = 0; dd < 8; dd++) sph[dd][l + 1] = phb[dd * NL + l];
    if (l < 8) { sph[l][0] = 0.0f; sph[l][NL + 1] = 0.0f; }
    __syncthreads();

    float acc[16];
#pragma unroll
    for (int i = 0; i < 16; i++) acc[i] = 0.0f;

#pragma unroll
    for (int dd = 0; dd < 8; dd++) {
        float v[3] = {sph[dd][l], sph[dd][l + 1], sph[dd][l + 2]};
        const float* wd = sWe + dd * 48;
#pragma unroll
        for (int lin = 0; lin < 48; lin += 4) {
            float4 w = *(const float4*)(wd + lin);
            acc[(lin + 0) / 3] += w.x * v[(lin + 0) % 3];
            acc[(lin + 1) / 3] += w.y * v[(lin + 1) % 3];
            acc[(lin + 2) / 3] += w.z * v[(lin + 2) % 3];
            acc[(lin + 3) / 3] += w.w * v[(lin + 3) % 3];
        }
    }
    float* outp = g_hpart + ((size_t)(c * NB + b) * NL + l) * 16;
#pragma unroll
    for (int i = 0; i < 16; i += 4)
        *(float4*)(outp + i) = make_float4(acc[i], acc[i + 1], acc[i + 2], acc[i + 3]);
}

// ---- K3b: reduce partials + bias + swish, fold h into t-invariant bases --
__global__ void k_conv_fin(const float* __restrict__ dur,
                           const float* __restrict__ cwb, const float* __restrict__ ccb,
                           const float* __restrict__ mwW, const float* __restrict__ mwb,
                           const float* __restrict__ mcW, const float* __restrict__ mcb) {
    int b = blockIdx.x, l = threadIdx.x;
    __shared__ float smw[40], smwb[4], smc[20], smcb[2];
    if (l < 40) smw[l] = mwW[l];
    if (l < 4) smwb[l] = mwb[l];
    if (l >= 64 && l < 84) smc[l - 64] = mcW[l - 64];
    if (l >= 96 && l < 98) smcb[l - 96] = mcb[l - 96];

    float acc[16];
#pragma unroll
    for (int i = 0; i < 16; i++) acc[i] = 0.0f;
#pragma unroll
    for (int c = 0; c < 32; c++) {
        const float* p = g_hpart + ((size_t)(c * NB + b) * NL + l) * 16;
#pragma unroll
        for (int i = 0; i < 16; i += 4) {
            float4 v = *(const float4*)(p + i);
            acc[i] += v.x; acc[i + 1] += v.y; acc[i + 2] += v.z; acc[i + 3] += v.w;
        }
    }
    float h[16];
#pragma unroll
    for (int idx = 0; idx < 16; idx++) {
        int br = idx >> 3, ch = idx & 7;
        float bias = (br ? ccb : cwb)[ch];
        float c0 = g_cwpb[br * 24 + ch * 3 + 0];
        float c1 = g_cwpb[br * 24 + ch * 3 + 1];
        float c2 = g_cwpb[br * 24 + ch * 3 + 2];
        bias += c0 + c1 + c2;
        if (l == 0) bias -= c0;
        if (l == NL - 1) bias -= c2;
        h[idx] = swishf(acc[idx] + bias);
    }
    __syncthreads();

    bool pad = (dur[b * NL + l] == 0.0f);
    float skv = g_sk[b * NL + l];
    float sdv = g_sd[b * NL + l];
    float E = pad ? 0.0f : (sdv - skv);
    float oms = pad ? 0.0f : (1.0f - skv);   // (t+1-sk) = t + oms
    float bzw[4];
#pragma unroll
    for (int q = 0; q < 4; q++) {
        float z = smwb[q] + oms * smw[q] + E * smw[4 + q];
#pragma unroll
        for (int ch = 0; ch < 8; ch++) z += (pad ? 0.0f : h[ch]) * smw[(2 + ch) * 4 + q];
        bzw[q] = z;
    }
    *(float4*)(g_bzw + (b * NL + l) * 4) = make_float4(bzw[0], bzw[1], bzw[2], bzw[3]);
    float bzc[2];
#pragma unroll
    for (int p = 0; p < 2; p++) {
        float z = smcb[p] + oms * smc[p] + E * smc[2 + p];
#pragma unroll
        for (int ch = 0; ch < 8; ch++) z += (pad ? 0.0f : h[8 + ch]) * smc[(2 + ch) * 2 + p];
        bzc[p] = z;
    }
    *(float2*)(g_bzc + (b * NL + l) * 2) = make_float2(bzc[0], bzc[1]);
    g_pad[b * NL + l] = pad ? 1.0f : 0.0f;
}

// ---------------- K4: M via tf32 MMA (R7 structure) -----------------------
__global__ __launch_bounds__(256) void k_mgemm2(const float* __restrict__ ph,
                                                const float* __restrict__ linw) {
    int b = blockIdx.z;
    int n0 = blockIdx.x * 128;
    int l0 = blockIdx.y * 128;
    int q = n0 >> 8;
    int o0 = n0 & 255;
    __shared__ __align__(16) float As[32][136];  // [k][l]
    __shared__ __align__(16) float Bs[32][136];  // [k][n]

    int tid = threadIdx.x;
    int wid = tid >> 5, lane = tid & 31;
    int warpRow = wid >> 1, warpCol = wid & 1;
    int g = lane >> 2, tg = lane & 3;

    const float* Ab = ph + (size_t)b * ND * NL;
    const float* Bb = linw + (size_t)q * 256 * 256;

    float acc[2][8][4];
#pragma unroll
    for (int mt = 0; mt < 2; mt++)
#pragma unroll
        for (int nt = 0; nt < 8; nt++)
#pragma unroll
            for (int j = 0; j < 4; j++) acc[mt][nt][j] = 0.0f;

    for (int k0 = 0; k0 < 256; k0 += 32) {
        __syncthreads();
#pragma unroll
        for (int i = 0; i < 4; i++) {
            int idx = i * 256 + tid;
            int r = idx >> 5, c4 = (idx & 31) * 4;
            float4 av = *(const float4*)(Ab + (size_t)(k0 + r) * NL + l0 + c4);
            As[r][c4 + 0] = to_tf32(av.x);
            As[r][c4 + 1] = to_tf32(av.y);
            As[r][c4 + 2] = to_tf32(av.z);
            As[r][c4 + 3] = to_tf32(av.w);
        }
#pragma unroll
        for (int i = 0; i < 4; i++) {
            int idx = i * 256 + tid;
            int r = idx >> 5, c4 = (idx & 31) * 4;
            float4 bv = *(const float4*)(Bb + (size_t)(k0 + r) * 256 + o0 + c4);
            Bs[r][c4 + 0] = to_tf32(bv.x);
            Bs[r][c4 + 1] = to_tf32(bv.y);
            Bs[r][c4 + 2] = to_tf32(bv.z);
            Bs[r][c4 + 3] = to_tf32(bv.w);
        }
        __syncthreads();
#pragma unroll
        for (int ks = 0; ks < 4; ks++) {
            int k = ks * 8;
            uint32_t af[2][4];
#pragma unroll
            for (int mt = 0; mt < 2; mt++) {
                int r0 = warpRow * 32 + mt * 16 + g;
                af[mt][0] = __float_as_uint(As[k + tg][r0]);
                af[mt][1] = __float_as_uint(As[k + tg][r0 + 8]);
                af[mt][2] = __float_as_uint(As[k + tg + 4][r0]);
                af[mt][3] = __float_as_uint(As[k + tg + 4][r0 + 8]);
            }
#pragma unroll
            for (int nt = 0; nt < 8; nt++) {
                int col = warpCol * 64 + nt * 8 + g;
                uint32_t b0 = __float_as_uint(Bs[k + tg][col]);
                uint32_t b1 = __float_as_uint(Bs[k + tg + 4][col]);
                mma_tf32(acc[0][nt], af[0][0], af[0][1], af[0][2], af[0][3], b0, b1);
                mma_tf32(acc[1][nt], af[1][0], af[1][1], af[1][2], af[1][3], b0, b1);
            }
        }
    }
    float* Mb = g_M + (size_t)b * 1024 * 256;
#pragma unroll
    for (int mt = 0; mt < 2; mt++) {
        int lr0 = warpRow * 32 + mt * 16 + g;
        int lr1 = lr0 + 8;
        int row0 = (l0 + lr0) * 4 + q;
        int row1 = (l0 + lr1) * 4 + q;
#pragma unroll
        for (int nt = 0; nt < 8; nt++) {
            int nl = warpCol * 64 + nt * 8 + 2 * tg;
            *(float2*)(Mb + (size_t)row0 * 256 + o0 + nl) =
                make_float2(to_tf32(acc[mt][nt][0]), to_tf32(acc[mt][nt][1]));
            *(float2*)(Mb + (size_t)row1 * 256 + o0 + nl) =
                make_float2(to_tf32(acc[mt][nt][2]), to_tf32(acc[mt][nt][3]));
        }
    }
}

// ---------------- K6: fused softmax-w + tf32 GEMM + wc epilogue -----------
// grid (1, 8, NB), 512 threads, BM=128 t-rows, BN=256, K=1024 (l*4+q)
// double-buffered As/Bs; B tiles via cp.async
#define SM_AS    0                  // 2 * 128*36 = 9216 floats
#define SM_BS    9216               // 2 * 32*264 = 16896
#define SM_SC    26112              // 8*256      = 2048
#define SM_SB    28160              // 256
#define SM_SWC   28416              // 128*8      = 1024
#define SM_MX    29440              // 128*4      = 512
#define SM_RS    29952              // 128*4      = 512
#define SM_TOTF  30464

__global__ __launch_bounds__(512) void k_final2(
        const float* __restrict__ lwb, const float* __restrict__ lcW,
        const float* __restrict__ lcb, const float* __restrict__ mwW,
        const float* __restrict__ mcW, float* __restrict__ out) {
    extern __shared__ float sm[];
    float (*sC)[256] = (float(*)[256])(sm + SM_SC);
    float* sB   = sm + SM_SB;
    float (*sWC)[8] = (float(*)[8])(sm + SM_SWC);
    float (*smx)[4] = (float(*)[4])(sm + SM_MX);
    float (*srs)[4] = (float(*)[4])(sm + SM_RS);
    uint32_t smem_base_u32 = (uint32_t)__cvta_generic_to_shared(sm);

    int b = blockIdx.z;
    int t0 = blockIdx.y * 128;
    int tid = threadIdx.x;
    int wid = tid >> 5, lane = tid & 31;
    int warpRow = wid >> 2, warpCol = wid & 3;
    int g = lane >> 2, tg = lane & 3;

    float W0[4] = {__ldg(mwW + 0), __ldg(mwW + 1), __ldg(mwW + 2), __ldg(mwW + 3)};
    float Wc0[2] = {__ldg(mcW + 0), __ldg(mcW + 1)};
    int flen = g_flen[b];
    const float* bzwb = g_bzw + b * NL * 4;
    const float* bzcb = g_bzc + b * NL * 2;
    const float* padb = g_pad + b * NL;
    const unsigned FULL = 0xffffffffu;

    // epilogue constants
    if (tid < 256) sB[tid] = lwb[tid] + lcb[tid];
    for (int i = tid; i < 8 * 256; i += 512)
        sC[i >> 8][i & 255] = lcW[i];

    // ---- prepass: per-row softmax stats + wc8 (warp wid owns rows 8w..8w+7)
#pragma unroll 1
    for (int rr = 0; rr < 8; rr++) {
        int r = wid * 8 + rr;
        int t = t0 + r;
        float tf = (float)t;
        if (t >= flen) {
            if (lane == 0) {
#pragma unroll
                for (int q = 0; q < 4; q++) { smx[r][q] = 0.0f; srs[r][q] = 0.0f; }
#pragma unroll
                for (int j = 0; j < 8; j++) sWC[r][j] = 0.0f;
            }
            continue;
        }
        float lg[8][4];
        float mx[4] = {-1e30f, -1e30f, -1e30f, -1e30f};
#pragma unroll
        for (int j = 0; j < 8; j++) {
            int l = j * 32 + lane;
            float4 bz = *(const float4*)(bzwb + l * 4);
            float pv = padb[l];
            float bza[4] = {bz.x, bz.y, bz.z, bz.w};
#pragma unroll
            for (int q = 0; q < 4; q++) {
                float s = swish_t(bza[q] + tf * W0[q]);
                lg[j][q] = (pv != 0.0f) ? -1e30f : s;
                mx[q] = fmaxf(mx[q], lg[j][q]);
            }
        }
#pragma unroll
        for (int off = 16; off > 0; off >>= 1)
#pragma unroll
            for (int q = 0; q < 4; q++)
                mx[q] = fmaxf(mx[q], __shfl_xor_sync(FULL, mx[q], off));
        float smv[4] = {0, 0, 0, 0};
#pragma unroll
        for (int j = 0; j < 8; j++)
#pragma unroll
            for (int q = 0; q < 4; q++) {
                float e = __expf(lg[j][q] - mx[q]);
                lg[j][q] = e;
                smv[q] += e;
            }
#pragma unroll
        for (int off = 16; off > 0; off >>= 1)
#pragma unroll
            for (int q = 0; q < 4; q++)
                smv[q] += __shfl_xor_sync(FULL, smv[q], off);
        float rs[4];
#pragma unroll
        for (int q = 0; q < 4; q++) rs[q] = __fdividef(1.0f, smv[q]);

        float wc[8] = {0, 0, 0, 0, 0, 0, 0, 0};
#pragma unroll
        for (int j = 0; j < 8; j++) {
            int l = j * 32 + lane;
            float2 bc = *(const float2*)(bzcb + l * 2);
            float cp0 = swish_t(bc.x + tf * Wc0[0]);
            float cp1 = swish_t(bc.y + tf * Wc0[1]);
#pragma unroll
            for (int q = 0; q < 4; q++) {
                float w = lg[j][q] * rs[q];
                wc[q * 2 + 0] += w * cp0;
                wc[q * 2 + 1] += w * cp1;
            }
        }
#pragma unroll
        for (int off = 16; off > 0; off >>= 1)
#pragma unroll
            for (int j = 0; j < 8; j++) wc[j] += __shfl_xor_sync(FULL, wc[j], off);
        if (lane == 0) {
#pragma unroll
            for (int q = 0; q < 4; q++) { smx[r][q] = mx[q]; srs[r][q] = rs[q]; }
#pragma unroll
            for (int j = 0; j < 8; j++) sWC[r][j] = wc[j];
        }
    }
    __syncthreads();

    // per-thread A-row constants (2 slots)
    int rA0 = tid >> 3, rA1 = 64 + (tid >> 3);
    int cA4 = (tid & 7) * 4;
    float tfA0 = (float)(t0 + rA0), tfA1 = (float)(t0 + rA1);
    float mxA0[4], rsA0[4], mxA1[4], rsA1[4];
#pragma unroll
    for (int q = 0; q < 4; q++) {
        mxA0[q] = smx[rA0][q]; rsA0[q] = srs[rA0][q];
        mxA1[q] = smx[rA1][q]; rsA1[q] = srs[rA1][q];
    }

    const float* Bb = g_M + (size_t)b * 1024 * 256;
    int rB = tid >> 6, cB4 = (tid & 63) * 4;   // B load coords (i adds 8 rows)

    float acc[2][8][4];
#pragma unroll
    for (int mt = 0; mt < 2; mt++)
#pragma unroll
        for (int nt = 0; nt < 8; nt++)
#pragma unroll
            for (int j = 0; j < 4; j++) acc[mt][nt][j] = 0.0f;

    // fill helpers
    auto fillA = [&](int buf, int k0) {
        float (*As)[36] = (float(*)[36])(sm + SM_AS + buf * 4608);
        int l = (k0 + cA4) >> 2;
        float4 bz = *(const float4*)(bzwb + l * 4);
        float pv = padb[l];
        float bza[4] = {bz.x, bz.y, bz.z, bz.w};
        float w0[4], w1[4];
#pragma unroll
        for (int q = 0; q < 4; q++) {
            float s0 = swish_t(bza[q] + tfA0 * W0[q]);
            s0 = (pv != 0.0f) ? -1e30f : s0;
            w0[q] = __expf(s0 - mxA0[q]) * rsA0[q];
            float s1 = swish_t(bza[q] + tfA1 * W0[q]);
            s1 = (pv != 0.0f) ? -1e30f : s1;
            w1[q] = __expf(s1 - mxA1[q]) * rsA1[q];
        }
        *(float4*)(&As[rA0][cA4]) = make_float4(to_tf32(w0[0]), to_tf32(w0[1]),
                                                to_tf32(w0[2]), to_tf32(w0[3]));
        *(float4*)(&As[rA1][cA4]) = make_float4(to_tf32(w1[0]), to_tf32(w1[1]),
                                                to_tf32(w1[2]), to_tf32(w1[3]));
    };
    auto fillB_async = [&](int buf, int k0) {
#pragma unroll
        for (int i = 0; i < 4; i++) {
            int r = i * 8 + rB;
            uint32_t saddr = smem_base_u32 +
                (uint32_t)((SM_BS + buf * 8448 + r * 264 + cB4) * 4);
            cp_async16(saddr, Bb + (size_t)(k0 + r) * 256 + cB4);
        }
        cp_commit();
    };

    // prologue: fill buffer 0 with chunk 0
    fillB_async(0, 0);
    fillA(0, 0);
    cp_wait0();
    __syncthreads();

    int cur = 0;
    for (int k0 = 0; k0 < 1024; k0 += 32) {
        int nxt = cur ^ 1;
        if (k0 + 32 < 1024) {
            fillB_async(nxt, k0 + 32);   // async DMA starts first
            fillA(nxt, k0 + 32);         // MUFU compute overlaps DMA
        }
        float (*As)[36]  = (float(*)[36])(sm + SM_AS + cur * 4608);
        float (*Bs)[264] = (float(*)[264])(sm + SM_BS + cur * 8448);
#pragma unroll
        for (int ks = 0; ks < 4; ks++) {
            int k = ks * 8;
            uint32_t af[2][4];
#pragma unroll
            for (int mt = 0; mt < 2; mt++) {
                int r0 = warpRow * 32 + mt * 16 + g;
                af[mt][0] = __float_as_uint(As[r0][k + tg]);
                af[mt][1] = __float_as_uint(As[r0 + 8][k + tg]);
                af[mt][2] = __float_as_uint(As[r0][k + tg + 4]);
                af[mt][3] = __float_as_uint(As[r0 + 8][k + tg + 4]);
            }
#pragma unroll
            for (int nt = 0; nt < 8; nt++) {
                int col = warpCol * 64 + nt * 8 + g;
                uint32_t b0 = __float_as_uint(Bs[k + tg][col]);
                uint32_t b1 = __float_as_uint(Bs[k + tg + 4][col]);
                mma_tf32(acc[0][nt], af[0][0], af[0][1], af[0][2], af[0][3], b0, b1);
                mma_tf32(acc[1][nt], af[1][0], af[1][1], af[1][2], af[1][3], b0, b1);
            }
        }
        cp_wait0();        // next B tile landed
        __syncthreads();   // + current reads done / next A stores visible
        cur = nxt;
    }

    // epilogue
#pragma unroll
    for (int mt = 0; mt < 2; mt++) {
        int lr0 = warpRow * 32 + mt * 16 + g;
        int lr1 = lr0 + 8;
        float wc0[8], wc1[8];
#pragma unroll
        for (int j = 0; j < 8; j++) { wc0[j] = sWC[lr0][j]; wc1[j] = sWC[lr1][j]; }
        int T0 = t0 + lr0, T1 = t0 + lr1;
#pragma unroll
        for (int nt = 0; nt < 8; nt++) {
            int nl = warpCol * 64 + nt * 8 + 2 * tg;
            float bias0 = sB[nl], bias1 = sB[nl + 1];
            float e00 = acc[mt][nt][0] + bias0, e01 = acc[mt][nt][1] + bias1;
            float e10 = acc[mt][nt][2] + bias0, e11 = acc[mt][nt][3] + bias1;
#pragma unroll
            for (int j = 0; j < 8; j++) {
                float c0v = sC[j][nl], c1v = sC[j][nl + 1];
                e00 += wc0[j] * c0v; e01 += wc0[j] * c1v;
                e10 += wc1[j] * c0v; e11 += wc1[j] * c1v;
            }
            if (T0 < NT)
                *(float2*)(out + ((size_t)(b * NT + T0)) * 256 + nl) = make_float2(e00, e01);
            if (T1 < NT)
                *(float2*)(out + ((size_t)(b * NT + T1)) * 256 + nl) = make_float2(e10, e11);
        }
    }
}

// ---------------------------------------------------------------------------
extern "C" void kernel_launch(void* const* d_in, const int* in_sizes, int n_in,
                              void* d_out, int out_size) {
    const float* durations = (const float*)d_in[0];
    const float* phoneme   = (const float*)d_in[1];
    // d_in[2] = phoneme_mask (unused; derived from durations == 0)
    const float* proj_w_W  = (const float*)d_in[3];
    const float* proj_w_b  = (const float*)d_in[4];
    const float* conv_w_W  = (const float*)d_in[5];
    const float* conv_w_b  = (const float*)d_in[6];
    const float* mlp_w_W   = (const float*)d_in[7];
    const float* mlp_w_b   = (const float*)d_in[8];
    const float* lin_w_W   = (const float*)d_in[9];
    const float* lin_w_b   = (const float*)d_in[10];
    const float* proj_c_W  = (const float*)d_in[11];
    const float* proj_c_b  = (const float*)d_in[12];
    const float* conv_c_W  = (const float*)d_in[13];
    const float* conv_c_b  = (const float*)d_in[14];
    const float* mlp_c_W   = (const float*)d_in[15];
    const float* mlp_c_b   = (const float*)d_in[16];
    const float* lin_c_W   = (const float*)d_in[17];
    const float* lin_c_b   = (const float*)d_in[18];
    float* out = (float*)d_out;

    static int smset = 0;
    if (!smset) {
        cudaFuncSetAttribute(k_final2, cudaFuncAttributeMaxDynamicSharedMemorySize,
                             SM_TOTF * sizeof(float));
        smset = 1;
    }

    k_scan<<<NB, NL>>>(durations);
    k_weff<<<dim3(3, 8, 2), ND>>>(proj_w_W, conv_w_W, proj_c_W, conv_c_W,
                                  proj_w_b, proj_c_b);
    k_conv_part<<<dim3(NB, 32), NL>>>(phoneme);
    k_conv_fin<<<NB, NL>>>(durations, conv_w_b, conv_c_b,
                           mlp_w_W, mlp_w_b, mlp_c_W, mlp_c_b);
    k_mgemm2<<<dim3(8, 2, NB), 256>>>(phoneme, lin_w_W);
    k_final2<<<dim3(1, 8, NB), 512, SM_TOTF * sizeof(float)>>>(
        lin_w_b, lin_c_W, lin_c_b, mlp_w_W, mlp_c_W, out);
}